// round 2
// baseline (speedup 1.0000x reference)
#include <cuda_runtime.h>
#include <cuda_bf16.h>

// SAGEConv copy_u_mean: out[d] = mean over edges e with dst[e]==d of x[src[e]]
// x: [N,32] f32, src/dst: [E] int32 (JAX x64 disabled downcasts int64->int32),
// out: [N,32] f32.
//
// Strategy: 8 threads per edge, each handling one float4 quad of the 32-wide
// feature row. x (12.8MB) is L2-resident; reductions use red.global.add.v4.f32
// (sm_90+) so each edge costs 8 vector REDs instead of 32 scalar ones.

#define MAX_NODES (1 << 17)  // 131072 >= 100000

__device__ float g_deg[MAX_NODES];

__global__ void zero_kernel(float4* __restrict__ out4, int out4_n, int n_nodes) {
    int t = blockIdx.x * blockDim.x + threadIdx.x;
    if (t < out4_n) out4[t] = make_float4(0.f, 0.f, 0.f, 0.f);
    if (t < n_nodes) g_deg[t] = 0.f;
}

__global__ void scatter_kernel(const float4* __restrict__ x4,
                               const int* __restrict__ src,
                               const int* __restrict__ dst,
                               float4* __restrict__ out4,
                               unsigned int total_threads) {
    unsigned int t = blockIdx.x * blockDim.x + threadIdx.x;
    if (t >= total_threads) return;
    unsigned int e = t >> 3;      // edge index
    unsigned int q = t & 7;       // quad within the 32-float row

    int s = src[e];
    int d = dst[e];

    float4 v = x4[(size_t)s * 8 + q];
    float4* p = out4 + (size_t)d * 8 + q;

    asm volatile("red.global.add.v4.f32 [%0], {%1, %2, %3, %4};"
                 :: "l"(p), "f"(v.x), "f"(v.y), "f"(v.z), "f"(v.w)
                 : "memory");

    if (q == 0) {
        atomicAdd(&g_deg[d], 1.0f);  // compiles to RED.E.ADD.F32 (no return)
    }
}

__global__ void div_kernel(float4* __restrict__ out4, int out4_n) {
    int t = blockIdx.x * blockDim.x + threadIdx.x;
    if (t >= out4_n) return;
    int node = t >> 3;
    float deg = g_deg[node];
    float inv = 1.0f / fmaxf(deg, 1.0f);
    float4 v = out4[t];
    v.x *= inv; v.y *= inv; v.z *= inv; v.w *= inv;
    out4[t] = v;
}

extern "C" void kernel_launch(void* const* d_in, const int* in_sizes, int n_in,
                              void* d_out, int out_size) {
    const float* x   = (const float*)d_in[0];
    const int*   src = (const int*)d_in[1];
    const int*   dst = (const int*)d_in[2];
    float* out = (float*)d_out;

    int n_nodes = in_sizes[0] / 32;
    int n_edges = in_sizes[1];
    int out4_n  = out_size / 4;          // number of float4 in out

    const int TPB = 256;

    // 1) zero output + degree scratch
    {
        int work = out4_n > n_nodes ? out4_n : n_nodes;
        int blocks = (work + TPB - 1) / TPB;
        zero_kernel<<<blocks, TPB>>>((float4*)out, out4_n, n_nodes);
    }

    // 2) scatter-add with vector REDs
    {
        unsigned int total = (unsigned int)n_edges * 8u;
        unsigned int blocks = (total + TPB - 1) / TPB;
        scatter_kernel<<<blocks, TPB>>>((const float4*)x, src, dst,
                                        (float4*)out, total);
    }

    // 3) divide by degree (clamped at 1)
    {
        int blocks = (out4_n + TPB - 1) / TPB;
        div_kernel<<<blocks, TPB>>>((float4*)out, out4_n);
    }
}

// round 3
// speedup vs baseline: 1.3739x; 1.3739x over previous
#include <cuda_runtime.h>
#include <cuda_bf16.h>

// SAGEConv copy_u_mean, pull formulation:
//   1) histogram in-degrees       2) exclusive scan -> CSR offsets
//   3) fill CSR buckets with src  4) per-node gather-sum + mean (single write)
// x: [N,32] f32 (12.8MB, L2-resident). src/dst: [E] int32. out: [N,32] f32.
// Avoids 12.8M float REDs (the 62us REDG floor of the push version).

#define N_MAX   131072     // >= 100000
#define E_MAX   1700000    // >= 1600000
#define SCAN_B  1024
#define MAX_BLOCKS_SCAN 256

__device__ int g_count[N_MAX];
__device__ int g_off[N_MAX];
__device__ int g_cursor[N_MAX];
__device__ int g_esrc[E_MAX];
__device__ int g_bsum[MAX_BLOCKS_SCAN];

// ---- K0: zero counts ----
__global__ void k_zero(int n) {
    int i = blockIdx.x * blockDim.x + threadIdx.x;
    if (i < n) g_count[i] = 0;
}

// ---- K1: in-degree histogram ----
__global__ void k_hist(const int* __restrict__ dst, int E) {
    int e = blockIdx.x * blockDim.x + threadIdx.x;
    if (e < E) atomicAdd(&g_count[dst[e]], 1);
}

// ---- K2a: per-block inclusive scan (Hillis-Steele), emits exclusive ----
__global__ void k_scan_block(int n) {
    __shared__ int sh[SCAN_B];
    int tid = threadIdx.x;
    int i = blockIdx.x * SCAN_B + tid;
    int v = (i < n) ? g_count[i] : 0;
    sh[tid] = v;
    __syncthreads();
    #pragma unroll
    for (int off = 1; off < SCAN_B; off <<= 1) {
        int t = (tid >= off) ? sh[tid - off] : 0;
        __syncthreads();
        sh[tid] += t;
        __syncthreads();
    }
    if (i < n) g_off[i] = sh[tid] - v;              // exclusive
    if (tid == SCAN_B - 1) g_bsum[blockIdx.x] = sh[tid];
}

// ---- K2b: serial scan of block sums (<=256 values) ----
__global__ void k_scan_sums(int nblocks) {
    if (threadIdx.x == 0 && blockIdx.x == 0) {
        int acc = 0;
        for (int b = 0; b < nblocks; b++) {
            int t = g_bsum[b];
            g_bsum[b] = acc;
            acc += t;
        }
    }
}

// ---- K2c: add block bases; seed cursors ----
__global__ void k_scan_add(int n) {
    int i = blockIdx.x * SCAN_B + threadIdx.x;
    if (i < n) {
        int o = g_off[i] + g_bsum[blockIdx.x];
        g_off[i] = o;
        g_cursor[i] = o;
    }
}

// ---- K3: scatter src ids into CSR buckets ----
__global__ void k_fill(const int* __restrict__ src,
                       const int* __restrict__ dst, int E) {
    int e = blockIdx.x * blockDim.x + threadIdx.x;
    if (e < E) {
        int d = dst[e];
        int pos = atomicAdd(&g_cursor[d], 1);
        g_esrc[pos] = src[e];
    }
}

// ---- K4: pull gather-sum + mean. 8 threads per node (one float4 quad each) ----
__global__ void k_gather(const float4* __restrict__ x4,
                         float4* __restrict__ out4,
                         int n_nodes) {
    unsigned int t = blockIdx.x * blockDim.x + threadIdx.x;
    unsigned int node = t >> 3;
    unsigned int q = t & 7;
    if (node >= (unsigned int)n_nodes) return;

    int beg = g_off[node];
    int cnt = g_count[node];
    int end = beg + cnt;

    float4 acc = make_float4(0.f, 0.f, 0.f, 0.f);
    int i = beg;
    // unroll-by-2 to expose load MLP
    for (; i + 1 < end; i += 2) {
        int s0 = g_esrc[i];
        int s1 = g_esrc[i + 1];
        float4 v0 = x4[(size_t)s0 * 8 + q];
        float4 v1 = x4[(size_t)s1 * 8 + q];
        acc.x += v0.x + v1.x;
        acc.y += v0.y + v1.y;
        acc.z += v0.z + v1.z;
        acc.w += v0.w + v1.w;
    }
    if (i < end) {
        int s = g_esrc[i];
        float4 v = x4[(size_t)s * 8 + q];
        acc.x += v.x; acc.y += v.y; acc.z += v.z; acc.w += v.w;
    }

    float inv = 1.0f / fmaxf((float)cnt, 1.0f);
    acc.x *= inv; acc.y *= inv; acc.z *= inv; acc.w *= inv;
    out4[(size_t)node * 8 + q] = acc;
}

extern "C" void kernel_launch(void* const* d_in, const int* in_sizes, int n_in,
                              void* d_out, int out_size) {
    const float* x   = (const float*)d_in[0];
    const int*   src = (const int*)d_in[1];
    const int*   dst = (const int*)d_in[2];
    float* out = (float*)d_out;

    int n_nodes = in_sizes[0] / 32;
    int E = in_sizes[1];

    const int TPB = 256;
    int nb_nodes = (n_nodes + TPB - 1) / TPB;
    int nb_edges = (E + TPB - 1) / TPB;
    int nb_scan  = (n_nodes + SCAN_B - 1) / SCAN_B;

    k_zero<<<nb_nodes, TPB>>>(n_nodes);
    k_hist<<<nb_edges, TPB>>>(dst, E);
    k_scan_block<<<nb_scan, SCAN_B>>>(n_nodes);
    k_scan_sums<<<1, 32>>>(nb_scan);
    k_scan_add<<<nb_scan, SCAN_B>>>(n_nodes);
    k_fill<<<nb_edges, TPB>>>(src, dst, E);

    unsigned int gtotal = (unsigned int)n_nodes * 8u;
    unsigned int gb = (gtotal + TPB - 1) / TPB;
    k_gather<<<gb, TPB>>>((const float4*)x, (float4*)out, n_nodes);
}